// round 9
// baseline (speedup 1.0000x reference)
#include <cuda_runtime.h>
#include <cuda_fp16.h>
#include <cstdint>

#define NS 50000
#define NT 50000
#define NN 100000
#define DD 128
#define CAP 2200000
#define NB  ((NN + 255) / 256)

// ---------------- scratch (device globals: no runtime allocation) ----------------
static __device__ __half g_xh[NN * DD];   // transformed features, fp16 (gather source)
static __device__ float g_agg[NN * DD];   // rows [0,NS): conv2 agg; [NS,NN): conv1
static __device__ float g_sc [4 * NN];    // as1 | ad1 | as2 | ad2
static __device__ float g_wv [4 * DD];
static __device__ int   g_deg[NN];
static __device__ int   g_rowptr[NN];
static __device__ int   g_cur[NN];
static __device__ int   g_part[512];
static __device__ int   g_esrc[CAP];
static __device__ float g_ew  [CAP];

// ---------------- 3xTF32 helpers --------------------------------------------------
__device__ __forceinline__ void split3(float v, uint32_t& hi, uint32_t& lo)
{
    uint32_t h = __float_as_uint(v) & 0xFFFFE000u;
    hi = h;
    lo = __float_as_uint(v - __uint_as_float(h)) & 0xFFFFE000u;
}

#define MMA_TF32(d, a0, a1, a2, a3, b0, b1)                                      \
    asm volatile("mma.sync.aligned.m16n8k8.row.col.f32.tf32.tf32.f32 "           \
        "{%0,%1,%2,%3}, {%4,%5,%6,%7}, {%8,%9}, {%0,%1,%2,%3};"                  \
        : "+f"((d)[0]), "+f"((d)[1]), "+f"((d)[2]), "+f"((d)[3])                 \
        : "r"(a0), "r"(a1), "r"(a2), "r"(a3), "r"(b0), "r"(b1))

// =============== GEMM: 64-row tile / 256 thr / 8 warps, presplit 3xTF32 ==========
// smem planes (floats): sAh[0], sAl[8448], sWh[16896], sWl[33792]; pitch 132.
// mode 0: output conv — C[M,128] = relu(A@W^T), f32 store to C.
// mode 1: input linear — x = A@W^T + bias, fp16 store to g_xh (+scoreOff rows),
//         fused attention scores into g_sc (atomic).
__global__ __launch_bounds__(256, 1)
void mma_gemm(const float* __restrict__ A, const float* __restrict__ W,
              const float* __restrict__ bias, float* __restrict__ C, int M,
              int mode, int scoreOff)
{
    extern __shared__ float sm[];
    float* sAh = sm;
    float* sAl = sm + 8448;
    float* sWh = sm + 16896;
    float* sWl = sm + 33792;
    const int tid  = threadIdx.x;
    const int row0 = blockIdx.x * 64;

    // preload + presplit W
    for (int i = tid; i < 4096; i += 256) {
        int n  = i >> 5;
        int k4 = (i & 31) << 2;
        float4 w = *(const float4*)(W + n * 128 + k4);
        uint32_t h0, l0, h1, l1, h2, l2, h3, l3;
        split3(w.x, h0, l0); split3(w.y, h1, l1);
        split3(w.z, h2, l2); split3(w.w, h3, l3);
        *(uint4*)(sWh + n * 132 + k4) = make_uint4(h0, h1, h2, h3);
        *(uint4*)(sWl + n * 132 + k4) = make_uint4(l0, l1, l2, l3);
    }
    // preload + presplit A
    for (int i = tid; i < 2048; i += 256) {
        int r  = i >> 5;
        int k4 = (i & 31) << 2;
        int gr = row0 + r;
        float4 v = make_float4(0.f, 0.f, 0.f, 0.f);
        if (gr < M) v = *(const float4*)(A + (size_t)gr * 128 + k4);
        uint32_t h0, l0, h1, l1, h2, l2, h3, l3;
        split3(v.x, h0, l0); split3(v.y, h1, l1);
        split3(v.z, h2, l2); split3(v.w, h3, l3);
        *(uint4*)(sAh + r * 132 + k4) = make_uint4(h0, h1, h2, h3);
        *(uint4*)(sAl + r * 132 + k4) = make_uint4(l0, l1, l2, l3);
    }
    __syncthreads();

    const int wid  = tid >> 5;
    const int lane = tid & 31;
    const int mw   = wid & 3;          // m-tile (16 rows)
    const int nb   = (wid >> 2) * 64;  // n-half base
    const int g    = lane >> 2;
    const int tq   = lane & 3;

    float acc[8][4] = {};

#pragma unroll
    for (int k0 = 0; k0 < 128; k0 += 8) {
        const int ra = (mw * 16 + g) * 132 + k0 + tq;
        uint32_t ah0 = __float_as_uint(sAh[ra]);
        uint32_t ah1 = __float_as_uint(sAh[ra + 8 * 132]);
        uint32_t ah2 = __float_as_uint(sAh[ra + 4]);
        uint32_t ah3 = __float_as_uint(sAh[ra + 8 * 132 + 4]);
        uint32_t al0 = __float_as_uint(sAl[ra]);
        uint32_t al1 = __float_as_uint(sAl[ra + 8 * 132]);
        uint32_t al2 = __float_as_uint(sAl[ra + 4]);
        uint32_t al3 = __float_as_uint(sAl[ra + 8 * 132 + 4]);
#pragma unroll
        for (int nt = 0; nt < 8; nt++) {
            const int rb = (nb + nt * 8 + g) * 132 + k0 + tq;
            uint32_t bh0 = __float_as_uint(sWh[rb]);
            uint32_t bh1 = __float_as_uint(sWh[rb + 4]);
            uint32_t bl0 = __float_as_uint(sWl[rb]);
            uint32_t bl1 = __float_as_uint(sWl[rb + 4]);
            MMA_TF32(acc[nt], ah0, ah1, ah2, ah3, bh0, bh1);
            MMA_TF32(acc[nt], al0, al1, al2, al3, bh0, bh1);
            MMA_TF32(acc[nt], ah0, ah1, ah2, ah3, bl0, bl1);
        }
    }

    // epilogue
    const int r0 = row0 + mw * 16 + g;
    const int r1 = r0 + 8;
    float s0[4] = {}, s1[4] = {};

#pragma unroll
    for (int nt = 0; nt < 8; nt++) {
        int c = nb + nt * 8 + tq * 2;
        float bx = 0.f, by = 0.f;
        if (mode == 1) { float2 b = *(const float2*)(bias + c); bx = b.x; by = b.y; }
        float o00 = acc[nt][0] + bx, o01 = acc[nt][1] + by;
        float o10 = acc[nt][2] + bx, o11 = acc[nt][3] + by;
        if (mode == 1) {
#pragma unroll
            for (int t = 0; t < 4; t++) {
                float2 w = *(const float2*)(g_wv + t * 128 + c);
                s0[t] += o00 * w.x + o01 * w.y;
                s1[t] += o10 * w.x + o11 * w.y;
            }
            if (r0 < M) *(__half2*)(g_xh + (size_t)(scoreOff + r0) * 128 + c) =
                __floats2half2_rn(o00, o01);
            if (r1 < M) *(__half2*)(g_xh + (size_t)(scoreOff + r1) * 128 + c) =
                __floats2half2_rn(o10, o11);
        } else {
            o00 = o00 > 0.f ? o00 : 0.f; o01 = o01 > 0.f ? o01 : 0.f;
            o10 = o10 > 0.f ? o10 : 0.f; o11 = o11 > 0.f ? o11 : 0.f;
            if (r0 < M) *(float2*)(C + (size_t)r0 * 128 + c) = make_float2(o00, o01);
            if (r1 < M) *(float2*)(C + (size_t)r1 * 128 + c) = make_float2(o10, o11);
        }
    }

    if (mode == 1) {
#pragma unroll
        for (int t = 0; t < 4; t++) {
            s0[t] += __shfl_xor_sync(0xFFFFFFFFu, s0[t], 1);
            s0[t] += __shfl_xor_sync(0xFFFFFFFFu, s0[t], 2);
            s1[t] += __shfl_xor_sync(0xFFFFFFFFu, s1[t], 1);
            s1[t] += __shfl_xor_sync(0xFFFFFFFFu, s1[t], 2);
        }
        if (tq == 0) {
#pragma unroll
            for (int t = 0; t < 4; t++) {
                if (r0 < M) atomicAdd(&g_sc[t * NN + scoreOff + r0], s0[t]);
                if (r1 < M) atomicAdd(&g_sc[t * NN + scoreOff + r1], s1[t]);
            }
        }
    }
}

// ---------------- precompute wv = W^T a (4 vectors of 128) -----------------------
__global__ void wvec_k(const float* __restrict__ W1, const float* __restrict__ a1s,
                       const float* __restrict__ a1d,
                       const float* __restrict__ W2, const float* __restrict__ a2s,
                       const float* __restrict__ a2d)
{
    int d = threadIdx.x;
    float s1 = 0.f, s2 = 0.f, s3 = 0.f, s4 = 0.f;
    for (int k = 0; k < 128; k++) {
        float w1 = W1[k * 128 + d], w2 = W2[k * 128 + d];
        s1 += w1 * a1s[k];
        s2 += w1 * a1d[k];
        s3 += w2 * a2s[k];
        s4 += w2 * a2d[k];
    }
    g_wv[d] = s1; g_wv[128 + d] = s2; g_wv[256 + d] = s3; g_wv[384 + d] = s4;
}

__device__ __forceinline__ float leaky(float e) { return e > 0.f ? e : 0.2f * e; }

// ---------------- combined edge decomposition ------------------------------------
__device__ __forceinline__ bool decomp_edge(int i, const int* edge, const int* paper,
                                            const int* author, int E, int Ep, int Ea,
                                            int& s, int& d, int& conv1)
{
    if (i < E) { s = edge[i]; d = edge[E + i] + NS; conv1 = 1; return true; }
    i -= E;
    if (i < Ea) { s = author[i]; d = author[Ea + i]; conv1 = 1; return d >= NS; }
    i -= Ea;
    if (i < NT) { s = d = NS + i; conv1 = 1; return true; }
    i -= NT;
    if (i < E) { s = edge[E + i] + NS; d = edge[i]; conv1 = 0; return true; }
    i -= E;
    if (i < Ep) { s = paper[i]; d = paper[Ep + i]; conv1 = 0; return d < NS; }
    i -= Ep;
    if (i < NS) { s = d = i; conv1 = 0; return true; }
    return false;
}

__global__ void hist_k(const int* __restrict__ edge, const int* __restrict__ paper,
                       const int* __restrict__ author, int E, int Ep, int Ea, int T)
{
    int i = blockIdx.x * blockDim.x + threadIdx.x;
    if (i >= T) return;
    int s, d, c1;
    if (decomp_edge(i, edge, paper, author, E, Ep, Ea, s, d, c1))
        atomicAdd(&g_deg[d], 1);
}

__global__ void scan1_k()
{
    __shared__ int sm[256];
    int t = threadIdx.x;
    int i = blockIdx.x * 256 + t;
    int v = (i < NN) ? g_deg[i] : 0;
    sm[t] = v; __syncthreads();
#pragma unroll
    for (int off = 1; off < 256; off <<= 1) {
        int u = (t >= off) ? sm[t - off] : 0;
        __syncthreads();
        sm[t] += u;
        __syncthreads();
    }
    if (i < NN) g_rowptr[i] = sm[t] - v;
    if (t == 255) g_part[blockIdx.x] = sm[255];
}

__global__ void scan2_k(int nb)
{
    __shared__ int sm[512];
    int t = threadIdx.x;
    int v = (t < nb) ? g_part[t] : 0;
    sm[t] = v; __syncthreads();
#pragma unroll
    for (int off = 1; off < 512; off <<= 1) {
        int u = (t >= off) ? sm[t - off] : 0;
        __syncthreads();
        sm[t] += u;
        __syncthreads();
    }
    if (t < nb) g_part[t] = sm[t] - v;
}

__global__ void scan3_k()
{
    int i = blockIdx.x * 256 + threadIdx.x;
    if (i >= NN) return;
    int rp = g_rowptr[i] + g_part[blockIdx.x];
    g_rowptr[i] = rp;
    g_cur[i]    = rp;
}

__global__ void fill_k(const int* __restrict__ edge, const int* __restrict__ paper,
                       const int* __restrict__ author, int E, int Ep, int Ea, int T)
{
    int i = blockIdx.x * blockDim.x + threadIdx.x;
    if (i >= T) return;
    int s, d, c1;
    if (!decomp_edge(i, edge, paper, author, E, Ep, Ea, s, d, c1)) return;
    float e = c1 ? (g_sc[s] + g_sc[NN + d]) : (g_sc[2 * NN + s] + g_sc[3 * NN + d]);
    float w = __expf(leaky(e));
    int pos = atomicAdd(&g_cur[d], 1);
    if (pos < CAP) { g_esrc[pos] = s; g_ew[pos] = w; }
}

// ---------------- SpMM: warp per dst row; fp16 gather, f32 accumulate ------------
__global__ __launch_bounds__(256)
void spmm_k()
{
    int r    = (blockIdx.x * blockDim.x + threadIdx.x) >> 5;
    int lane = threadIdx.x & 31;
    if (r >= NN) return;
    int start = g_rowptr[r];
    int n     = g_deg[r];
    float4 acc = make_float4(0.f, 0.f, 0.f, 0.f);
    float  den = 0.f;
#pragma unroll 2
    for (int e = 0; e < n; e++) {
        int   src = __ldg(g_esrc + start + e);
        float w   = __ldg(g_ew   + start + e);
        uint2 u = *(const uint2*)(g_xh + (size_t)src * 128 + lane * 4);
        float2 f0 = __half22float2(*(__half2*)&u.x);
        float2 f1 = __half22float2(*(__half2*)&u.y);
        acc.x += w * f0.x; acc.y += w * f0.y;
        acc.z += w * f1.x; acc.w += w * f1.y;
        den   += w;
    }
    float rc = __frcp_rn(den + 1e-16f);
    acc.x *= rc; acc.y *= rc; acc.z *= rc; acc.w *= rc;
    *(float4*)(g_agg + (size_t)r * 128 + lane * 4) = acc;
}

// ---------------- host launch -----------------------------------------------------
extern "C" void kernel_launch(void* const* d_in, const int* in_sizes, int n_in,
                              void* d_out, int out_size)
{
    const int* edge   = (const int*)d_in[0];
    const int* paper  = (const int*)d_in[1];
    const int* author = (const int*)d_in[2];
    const float* x_s = (const float*)d_in[3];
    const float* x_t = (const float*)d_in[4];
    const float* Ws  = (const float*)d_in[5];
    const float* bs  = (const float*)d_in[6];
    const float* Wt  = (const float*)d_in[7];
    const float* bt  = (const float*)d_in[8];
    const float* W1  = (const float*)d_in[9];
    const float* a1s = (const float*)d_in[10];
    const float* a1d = (const float*)d_in[11];
    const float* W2  = (const float*)d_in[12];
    const float* a2s = (const float*)d_in[13];
    const float* a2d = (const float*)d_in[14];

    const int E  = in_sizes[0] / 2;
    const int Ep = in_sizes[1] / 2;
    const int Ea = in_sizes[2] / 2;
    const int T  = 2 * E + Ea + Ep + NS + NT;

    float *pagg, *psc;
    cudaGetSymbolAddress((void**)&pagg, g_agg);
    cudaGetSymbolAddress((void**)&psc,  g_sc);
    int* pdeg;
    cudaGetSymbolAddress((void**)&pdeg, g_deg);

    float* out = (float*)d_out;
    float* out_s = out;                     // conv2 result rows [0, NS)
    float* out_t = out + (size_t)NS * DD;   // conv1 result rows [NS, NN)

    const int GEMM_SMEM = (2 * 64 * 132 + 2 * 128 * 132) * 4;  // 202752 B
    cudaFuncSetAttribute((const void*)mma_gemm,
                         cudaFuncAttributeMaxDynamicSharedMemorySize, GEMM_SMEM);

    // 0. zero degree histogram + score accumulators
    cudaMemsetAsync(pdeg, 0, NN * sizeof(int), 0);
    cudaMemsetAsync(psc,  0, 4 * NN * sizeof(float), 0);

    // 1. score projection vectors, then input linears (fp16 x + fused scores)
    wvec_k<<<1, 128>>>(W1, a1s, a1d, W2, a2s, a2d);
    mma_gemm<<<(NS + 63) / 64, 256, GEMM_SMEM>>>(x_s, Ws, bs, nullptr, NS, 1, 0);
    mma_gemm<<<(NT + 63) / 64, 256, GEMM_SMEM>>>(x_t, Wt, bt, nullptr, NT, 1, NS);

    // 2. CSR build over both convs' kept edges
    const int TB = 256;
    hist_k<<<(T + TB - 1) / TB, TB>>>(edge, paper, author, E, Ep, Ea, T);
    scan1_k<<<NB, 256>>>();
    scan2_k<<<1, 512>>>(NB);
    scan3_k<<<NB, 256>>>();
    fill_k<<<(T + TB - 1) / TB, TB>>>(edge, paper, author, E, Ep, Ea, T);

    // 3. SpMM: normalized aggregation of fp16 x rows
    spmm_k<<<(NN * 32 + TB - 1) / TB, TB>>>();

    // 4. output transforms: out = relu( agg @ W^T )
    mma_gemm<<<(NT + 63) / 64, 256, GEMM_SMEM>>>(pagg + (size_t)NS * DD, W1, nullptr, out_t, NT, 0, 0);
    mma_gemm<<<(NS + 63) / 64, 256, GEMM_SMEM>>>(pagg, W2, nullptr, out_s, NS, 0, 0);
}

// round 10
// speedup vs baseline: 1.3353x; 1.3353x over previous
#include <cuda_runtime.h>
#include <cstdint>

#define NS 50000
#define NT 50000
#define NN 100000
#define DD 128
#define CAP 2200000
#define NB  ((NN + 255) / 256)

// ---------------- scratch (device globals: no runtime allocation) ----------------
static __device__ float g_x  [NN * DD];
static __device__ float g_agg[NN * DD];   // rows [0,NS): conv2 agg; [NS,NN): conv1
static __device__ float g_sc [4 * NN];    // as1 | ad1 | as2 | ad2
static __device__ float g_wv [4 * DD];
static __device__ int   g_deg[NN];
static __device__ int   g_rowptr[NN];
static __device__ int   g_cur[NN];
static __device__ int   g_part[512];
static __device__ int   g_esrc[CAP];
static __device__ float g_ew  [CAP];

// ---------------- TF32 helpers ----------------------------------------------------
__device__ __forceinline__ uint32_t to_tf32(float f)
{
    uint32_t r;
    asm("cvt.rna.tf32.f32 %0, %1;" : "=r"(r) : "f"(f));
    return r;
}

#define MMA_TF32(d, a0, a1, a2, a3, b0, b1)                                      \
    asm volatile("mma.sync.aligned.m16n8k8.row.col.f32.tf32.tf32.f32 "           \
        "{%0,%1,%2,%3}, {%4,%5,%6,%7}, {%8,%9}, {%0,%1,%2,%3};"                  \
        : "+f"((d)[0]), "+f"((d)[1]), "+f"((d)[2]), "+f"((d)[3])                 \
        : "r"(a0), "r"(a1), "r"(a2), "r"(a3), "r"(b0), "r"(b1))

// =============== GEMM: C[M,128] = A[M,128] @ W[128,128]^T, 2-pass TF32 ===========
// 64-row tile / 256 threads / 8 warps (4 m-tiles x 2 n-halves).
// A error-compensated (Ah+Al), B single rounded tf32: err ~ 2^-12 relative.
__global__ __launch_bounds__(256)
void mma_gemm(const float* __restrict__ A, const float* __restrict__ W,
              const float* __restrict__ bias, float* __restrict__ C, int M,
              int doRelu, int doScores, int scoreOff)
{
    extern __shared__ float sm[];
    float* sA = sm;              // 64 x 132
    float* sW = sm + 64 * 132;   // 128 x 132 (W as-is: [n][k])
    const int tid  = threadIdx.x;
    const int row0 = blockIdx.x * 64;

    for (int i = tid; i < 4096; i += 256) {
        int n  = i >> 5;
        int k4 = (i & 31) << 2;
        *(float4*)(sW + n * 132 + k4) = *(const float4*)(W + n * 128 + k4);
    }
    for (int i = tid; i < 2048; i += 256) {
        int r  = i >> 5;
        int k4 = (i & 31) << 2;
        int gr = row0 + r;
        float4 v = make_float4(0.f, 0.f, 0.f, 0.f);
        if (gr < M) v = *(const float4*)(A + (size_t)gr * 128 + k4);
        *(float4*)(sA + r * 132 + k4) = v;
    }
    __syncthreads();

    const int wid  = tid >> 5;
    const int lane = tid & 31;
    const int mw   = wid & 3;          // m-tile (16 rows)
    const int nb   = (wid >> 2) * 64;  // n-half base
    const int g    = lane >> 2;
    const int tq   = lane & 3;

    float acc[8][4] = {};

#pragma unroll
    for (int k0 = 0; k0 < 128; k0 += 8) {
        const int ra = (mw * 16 + g) * 132 + k0 + tq;
        float a0 = sA[ra], a1 = sA[ra + 8 * 132], a2 = sA[ra + 4], a3 = sA[ra + 8 * 132 + 4];
        uint32_t ah0 = to_tf32(a0), ah1 = to_tf32(a1), ah2 = to_tf32(a2), ah3 = to_tf32(a3);
        uint32_t al0 = to_tf32(a0 - __uint_as_float(ah0));
        uint32_t al1 = to_tf32(a1 - __uint_as_float(ah1));
        uint32_t al2 = to_tf32(a2 - __uint_as_float(ah2));
        uint32_t al3 = to_tf32(a3 - __uint_as_float(ah3));
#pragma unroll
        for (int nt = 0; nt < 8; nt++) {
            const int rb = (nb + nt * 8 + g) * 132 + k0 + tq;
            uint32_t bh0 = to_tf32(sW[rb]);
            uint32_t bh1 = to_tf32(sW[rb + 4]);
            MMA_TF32(acc[nt], ah0, ah1, ah2, ah3, bh0, bh1);
            MMA_TF32(acc[nt], al0, al1, al2, al3, bh0, bh1);
        }
    }

    // epilogue
    const int r0 = row0 + mw * 16 + g;
    const int r1 = r0 + 8;
    float s0[4] = {}, s1[4] = {};

#pragma unroll
    for (int nt = 0; nt < 8; nt++) {
        int c = nb + nt * 8 + tq * 2;
        float bx = 0.f, by = 0.f;
        if (bias) { float2 b = *(const float2*)(bias + c); bx = b.x; by = b.y; }
        float o00 = acc[nt][0] + bx, o01 = acc[nt][1] + by;
        float o10 = acc[nt][2] + bx, o11 = acc[nt][3] + by;
        if (doScores) {
#pragma unroll
            for (int t = 0; t < 4; t++) {
                float2 w = *(const float2*)(g_wv + t * 128 + c);
                s0[t] += o00 * w.x + o01 * w.y;
                s1[t] += o10 * w.x + o11 * w.y;
            }
        }
        if (doRelu) {
            o00 = o00 > 0.f ? o00 : 0.f; o01 = o01 > 0.f ? o01 : 0.f;
            o10 = o10 > 0.f ? o10 : 0.f; o11 = o11 > 0.f ? o11 : 0.f;
        }
        if (r0 < M) *(float2*)(C + (size_t)r0 * 128 + c) = make_float2(o00, o01);
        if (r1 < M) *(float2*)(C + (size_t)r1 * 128 + c) = make_float2(o10, o11);
    }

    if (doScores) {
#pragma unroll
        for (int t = 0; t < 4; t++) {
            s0[t] += __shfl_xor_sync(0xFFFFFFFFu, s0[t], 1);
            s0[t] += __shfl_xor_sync(0xFFFFFFFFu, s0[t], 2);
            s1[t] += __shfl_xor_sync(0xFFFFFFFFu, s1[t], 1);
            s1[t] += __shfl_xor_sync(0xFFFFFFFFu, s1[t], 2);
        }
        if (tq == 0) {
#pragma unroll
            for (int t = 0; t < 4; t++) {
                if (r0 < M) atomicAdd(&g_sc[t * NN + scoreOff + r0], s0[t]);
                if (r1 < M) atomicAdd(&g_sc[t * NN + scoreOff + r1], s1[t]);
            }
        }
    }
}

// ---------------- precompute wv = W^T a (4 vectors of 128) -----------------------
__global__ void wvec_k(const float* __restrict__ W1, const float* __restrict__ a1s,
                       const float* __restrict__ a1d,
                       const float* __restrict__ W2, const float* __restrict__ a2s,
                       const float* __restrict__ a2d)
{
    int d = threadIdx.x;
    float s1 = 0.f, s2 = 0.f, s3 = 0.f, s4 = 0.f;
    for (int k = 0; k < 128; k++) {
        float w1 = W1[k * 128 + d], w2 = W2[k * 128 + d];
        s1 += w1 * a1s[k];
        s2 += w1 * a1d[k];
        s3 += w2 * a2s[k];
        s4 += w2 * a2d[k];
    }
    g_wv[d] = s1; g_wv[128 + d] = s2; g_wv[256 + d] = s3; g_wv[384 + d] = s4;
}

__device__ __forceinline__ float leaky(float e) { return e > 0.f ? e : 0.2f * e; }

// ---------------- combined edge decomposition ------------------------------------
__device__ __forceinline__ bool decomp_edge(int i, const int* edge, const int* paper,
                                            const int* author, int E, int Ep, int Ea,
                                            int& s, int& d, int& conv1)
{
    if (i < E) { s = edge[i]; d = edge[E + i] + NS; conv1 = 1; return true; }
    i -= E;
    if (i < Ea) { s = author[i]; d = author[Ea + i]; conv1 = 1; return d >= NS; }
    i -= Ea;
    if (i < NT) { s = d = NS + i; conv1 = 1; return true; }
    i -= NT;
    if (i < E) { s = edge[E + i] + NS; d = edge[i]; conv1 = 0; return true; }
    i -= E;
    if (i < Ep) { s = paper[i]; d = paper[Ep + i]; conv1 = 0; return d < NS; }
    i -= Ep;
    if (i < NS) { s = d = i; conv1 = 0; return true; }
    return false;
}

__global__ void hist_k(const int* __restrict__ edge, const int* __restrict__ paper,
                       const int* __restrict__ author, int E, int Ep, int Ea, int T)
{
    int i = blockIdx.x * blockDim.x + threadIdx.x;
    if (i >= T) return;
    int s, d, c1;
    if (decomp_edge(i, edge, paper, author, E, Ep, Ea, s, d, c1))
        atomicAdd(&g_deg[d], 1);
}

__global__ void scan1_k()
{
    __shared__ int sm[256];
    int t = threadIdx.x;
    int i = blockIdx.x * 256 + t;
    int v = (i < NN) ? g_deg[i] : 0;
    sm[t] = v; __syncthreads();
#pragma unroll
    for (int off = 1; off < 256; off <<= 1) {
        int u = (t >= off) ? sm[t - off] : 0;
        __syncthreads();
        sm[t] += u;
        __syncthreads();
    }
    if (i < NN) g_rowptr[i] = sm[t] - v;
    if (t == 255) g_part[blockIdx.x] = sm[255];
}

__global__ void scan2_k(int nb)
{
    __shared__ int sm[512];
    int t = threadIdx.x;
    int v = (t < nb) ? g_part[t] : 0;
    sm[t] = v; __syncthreads();
#pragma unroll
    for (int off = 1; off < 512; off <<= 1) {
        int u = (t >= off) ? sm[t - off] : 0;
        __syncthreads();
        sm[t] += u;
        __syncthreads();
    }
    if (t < nb) g_part[t] = sm[t] - v;
}

__global__ void scan3_k()
{
    int i = blockIdx.x * 256 + threadIdx.x;
    if (i >= NN) return;
    int rp = g_rowptr[i] + g_part[blockIdx.x];
    g_rowptr[i] = rp;
    g_cur[i]    = rp;
}

__global__ void fill_k(const int* __restrict__ edge, const int* __restrict__ paper,
                       const int* __restrict__ author, int E, int Ep, int Ea, int T)
{
    int i = blockIdx.x * blockDim.x + threadIdx.x;
    if (i >= T) return;
    int s, d, c1;
    if (!decomp_edge(i, edge, paper, author, E, Ep, Ea, s, d, c1)) return;
    float e = c1 ? (g_sc[s] + g_sc[NN + d]) : (g_sc[2 * NN + s] + g_sc[3 * NN + d]);
    float w = __expf(leaky(e));
    int pos = atomicAdd(&g_cur[d], 1);
    if (pos < CAP) { g_esrc[pos] = s; g_ew[pos] = w; }
}

// ---------------- SpMM: warp per dst row; agg[r] = (sum w*x[src]) / (sum w) ------
__global__ __launch_bounds__(256)
void spmm_k(const float* __restrict__ x)
{
    int r    = (blockIdx.x * blockDim.x + threadIdx.x) >> 5;
    int lane = threadIdx.x & 31;
    if (r >= NN) return;
    int start = g_rowptr[r];
    int n     = g_deg[r];
    float4 acc = make_float4(0.f, 0.f, 0.f, 0.f);
    float  den = 0.f;
#pragma unroll 2
    for (int e = 0; e < n; e++) {
        int   src = __ldg(g_esrc + start + e);
        float w   = __ldg(g_ew   + start + e);
        float4 xv = *(const float4*)(x + (size_t)src * 128 + lane * 4);
        acc.x += w * xv.x; acc.y += w * xv.y;
        acc.z += w * xv.z; acc.w += w * xv.w;
        den   += w;
    }
    float rc = __frcp_rn(den + 1e-16f);
    acc.x *= rc; acc.y *= rc; acc.z *= rc; acc.w *= rc;
    *(float4*)(g_agg + (size_t)r * 128 + lane * 4) = acc;
}

// ---------------- host launch -----------------------------------------------------
extern "C" void kernel_launch(void* const* d_in, const int* in_sizes, int n_in,
                              void* d_out, int out_size)
{
    const int* edge   = (const int*)d_in[0];
    const int* paper  = (const int*)d_in[1];
    const int* author = (const int*)d_in[2];
    const float* x_s = (const float*)d_in[3];
    const float* x_t = (const float*)d_in[4];
    const float* Ws  = (const float*)d_in[5];
    const float* bs  = (const float*)d_in[6];
    const float* Wt  = (const float*)d_in[7];
    const float* bt  = (const float*)d_in[8];
    const float* W1  = (const float*)d_in[9];
    const float* a1s = (const float*)d_in[10];
    const float* a1d = (const float*)d_in[11];
    const float* W2  = (const float*)d_in[12];
    const float* a2s = (const float*)d_in[13];
    const float* a2d = (const float*)d_in[14];

    const int E  = in_sizes[0] / 2;
    const int Ep = in_sizes[1] / 2;
    const int Ea = in_sizes[2] / 2;
    const int T  = 2 * E + Ea + Ep + NS + NT;

    float *px, *pagg, *psc;
    cudaGetSymbolAddress((void**)&px,   g_x);
    cudaGetSymbolAddress((void**)&pagg, g_agg);
    cudaGetSymbolAddress((void**)&psc,  g_sc);
    int* pdeg;
    cudaGetSymbolAddress((void**)&pdeg, g_deg);

    float* out = (float*)d_out;
    float* out_s = out;                     // conv2 result rows [0, NS)
    float* out_t = out + (size_t)NS * DD;   // conv1 result rows [NS, NN)

    const int GEMM_SMEM = (64 * 132 + 128 * 132) * 4;  // 101376 B
    cudaFuncSetAttribute((const void*)mma_gemm,
                         cudaFuncAttributeMaxDynamicSharedMemorySize, GEMM_SMEM);

    // 0. zero degree histogram + score accumulators
    cudaMemsetAsync(pdeg, 0, NN * sizeof(int), 0);
    cudaMemsetAsync(psc,  0, 4 * NN * sizeof(float), 0);

    // 1. score projection vectors, then input linears with fused score epilogue
    wvec_k<<<1, 128>>>(W1, a1s, a1d, W2, a2s, a2d);
    mma_gemm<<<(NS + 63) / 64, 256, GEMM_SMEM>>>(x_s, Ws, bs, px, NS, 0, 1, 0);
    mma_gemm<<<(NT + 63) / 64, 256, GEMM_SMEM>>>(x_t, Wt, bt, px + (size_t)NS * DD, NT, 0, 1, NS);

    // 2. CSR build over both convs' kept edges
    const int TB = 256;
    hist_k<<<(T + TB - 1) / TB, TB>>>(edge, paper, author, E, Ep, Ea, T);
    scan1_k<<<NB, 256>>>();
    scan2_k<<<1, 512>>>(NB);
    scan3_k<<<NB, 256>>>();
    fill_k<<<(T + TB - 1) / TB, TB>>>(edge, paper, author, E, Ep, Ea, T);

    // 3. SpMM: normalized aggregation of x rows
    spmm_k<<<(NN * 32 + TB - 1) / TB, TB>>>(px);

    // 4. output transforms: out = relu( agg @ W^T )
    mma_gemm<<<(NT + 63) / 64, 256, GEMM_SMEM>>>(pagg + (size_t)NS * DD, W1, nullptr, out_t, NT, 1, 0, 0);
    mma_gemm<<<(NS + 63) / 64, 256, GEMM_SMEM>>>(pagg, W2, nullptr, out_s, NS, 1, 0, 0);
}

// round 11
// speedup vs baseline: 1.3853x; 1.0374x over previous
#include <cuda_runtime.h>
#include <cuda_fp16.h>
#include <cstdint>

#define NS 50000
#define NT 50000
#define NN 100000
#define DD 128
#define CAP 2200000
#define NB  ((NN + 255) / 256)

// ---------------- scratch (device globals: no runtime allocation) ----------------
static __device__ __half g_xh[NN * DD];   // transformed features, fp16 (gather source)
static __device__ float g_agg[NN * DD];   // rows [0,NS): conv2 agg; [NS,NN): conv1
static __device__ float g_sc [4 * NN];    // as1 | ad1 | as2 | ad2
static __device__ float g_wv [4 * DD];
static __device__ int   g_deg[NN];
static __device__ int   g_rowptr[NN];
static __device__ int   g_cur[NN];
static __device__ int   g_part[512];
static __device__ int   g_esrc[CAP];
static __device__ float g_ew  [CAP];

// ---------------- TF32 helpers ----------------------------------------------------
__device__ __forceinline__ uint32_t to_tf32(float f)
{
    uint32_t r;
    asm("cvt.rna.tf32.f32 %0, %1;" : "=r"(r) : "f"(f));
    return r;
}

#define MMA_TF32(d, a0, a1, a2, a3, b0, b1)                                      \
    asm volatile("mma.sync.aligned.m16n8k8.row.col.f32.tf32.tf32.f32 "           \
        "{%0,%1,%2,%3}, {%4,%5,%6,%7}, {%8,%9}, {%0,%1,%2,%3};"                  \
        : "+f"((d)[0]), "+f"((d)[1]), "+f"((d)[2]), "+f"((d)[3])                 \
        : "r"(a0), "r"(a1), "r"(a2), "r"(a3), "r"(b0), "r"(b1))

// =============== GEMM: C = A[M,128] @ W[128,128]^T, 2-pass TF32 ==================
// 64-row tile / 256 threads / 8 warps (4 m-tiles x 2 n-halves).
// A error-compensated (Ah+Al); W pre-rounded to tf32 in smem at load time.
// mode doScores=1 (input linear): +bias, fp16 store to g_xh, fused scores to g_sc.
// mode doScores=0 (output conv):  relu, f32 store to C.
__global__ __launch_bounds__(256)
void mma_gemm(const float* __restrict__ A, const float* __restrict__ W,
              const float* __restrict__ bias, float* __restrict__ C, int M,
              int doRelu, int doScores, int scoreOff)
{
    extern __shared__ float sm[];
    float* sA = sm;              // 64 x 132
    float* sW = sm + 64 * 132;   // 128 x 132, tf32-pre-rounded W ([n][k])
    const int tid  = threadIdx.x;
    const int row0 = blockIdx.x * 64;

    for (int i = tid; i < 4096; i += 256) {
        int n  = i >> 5;
        int k4 = (i & 31) << 2;
        float4 w = *(const float4*)(W + n * 128 + k4);
        uint4 t;
        t.x = to_tf32(w.x); t.y = to_tf32(w.y);
        t.z = to_tf32(w.z); t.w = to_tf32(w.w);
        *(uint4*)(sW + n * 132 + k4) = t;
    }
    for (int i = tid; i < 2048; i += 256) {
        int r  = i >> 5;
        int k4 = (i & 31) << 2;
        int gr = row0 + r;
        float4 v = make_float4(0.f, 0.f, 0.f, 0.f);
        if (gr < M) v = *(const float4*)(A + (size_t)gr * 128 + k4);
        *(float4*)(sA + r * 132 + k4) = v;
    }
    __syncthreads();

    const int wid  = tid >> 5;
    const int lane = tid & 31;
    const int mw   = wid & 3;          // m-tile (16 rows)
    const int nb   = (wid >> 2) * 64;  // n-half base
    const int g    = lane >> 2;
    const int tq   = lane & 3;

    float acc[8][4] = {};

#pragma unroll
    for (int k0 = 0; k0 < 128; k0 += 8) {
        const int ra = (mw * 16 + g) * 132 + k0 + tq;
        float a0 = sA[ra], a1 = sA[ra + 8 * 132], a2 = sA[ra + 4], a3 = sA[ra + 8 * 132 + 4];
        uint32_t ah0 = to_tf32(a0), ah1 = to_tf32(a1), ah2 = to_tf32(a2), ah3 = to_tf32(a3);
        uint32_t al0 = to_tf32(a0 - __uint_as_float(ah0));
        uint32_t al1 = to_tf32(a1 - __uint_as_float(ah1));
        uint32_t al2 = to_tf32(a2 - __uint_as_float(ah2));
        uint32_t al3 = to_tf32(a3 - __uint_as_float(ah3));
#pragma unroll
        for (int nt = 0; nt < 8; nt++) {
            const int rb = (nb + nt * 8 + g) * 132 + k0 + tq;
            uint32_t bh0 = __float_as_uint(sW[rb]);
            uint32_t bh1 = __float_as_uint(sW[rb + 4]);
            MMA_TF32(acc[nt], ah0, ah1, ah2, ah3, bh0, bh1);
            MMA_TF32(acc[nt], al0, al1, al2, al3, bh0, bh1);
        }
    }

    // epilogue
    const int r0 = row0 + mw * 16 + g;
    const int r1 = r0 + 8;
    float s0[4] = {}, s1[4] = {};

#pragma unroll
    for (int nt = 0; nt < 8; nt++) {
        int c = nb + nt * 8 + tq * 2;
        float bx = 0.f, by = 0.f;
        if (bias) { float2 b = *(const float2*)(bias + c); bx = b.x; by = b.y; }
        float o00 = acc[nt][0] + bx, o01 = acc[nt][1] + by;
        float o10 = acc[nt][2] + bx, o11 = acc[nt][3] + by;
        if (doScores) {
#pragma unroll
            for (int t = 0; t < 4; t++) {
                float2 w = *(const float2*)(g_wv + t * 128 + c);
                s0[t] += o00 * w.x + o01 * w.y;
                s1[t] += o10 * w.x + o11 * w.y;
            }
            if (r0 < M) *(__half2*)(g_xh + (size_t)(scoreOff + r0) * 128 + c) =
                __floats2half2_rn(o00, o01);
            if (r1 < M) *(__half2*)(g_xh + (size_t)(scoreOff + r1) * 128 + c) =
                __floats2half2_rn(o10, o11);
        } else {
            if (doRelu) {
                o00 = o00 > 0.f ? o00 : 0.f; o01 = o01 > 0.f ? o01 : 0.f;
                o10 = o10 > 0.f ? o10 : 0.f; o11 = o11 > 0.f ? o11 : 0.f;
            }
            if (r0 < M) *(float2*)(C + (size_t)r0 * 128 + c) = make_float2(o00, o01);
            if (r1 < M) *(float2*)(C + (size_t)r1 * 128 + c) = make_float2(o10, o11);
        }
    }

    if (doScores) {
#pragma unroll
        for (int t = 0; t < 4; t++) {
            s0[t] += __shfl_xor_sync(0xFFFFFFFFu, s0[t], 1);
            s0[t] += __shfl_xor_sync(0xFFFFFFFFu, s0[t], 2);
            s1[t] += __shfl_xor_sync(0xFFFFFFFFu, s1[t], 1);
            s1[t] += __shfl_xor_sync(0xFFFFFFFFu, s1[t], 2);
        }
        if (tq == 0) {
#pragma unroll
            for (int t = 0; t < 4; t++) {
                if (r0 < M) atomicAdd(&g_sc[t * NN + scoreOff + r0], s0[t]);
                if (r1 < M) atomicAdd(&g_sc[t * NN + scoreOff + r1], s1[t]);
            }
        }
    }
}

// ---------------- precompute wv = W^T a (4 vectors of 128) -----------------------
__global__ void wvec_k(const float* __restrict__ W1, const float* __restrict__ a1s,
                       const float* __restrict__ a1d,
                       const float* __restrict__ W2, const float* __restrict__ a2s,
                       const float* __restrict__ a2d)
{
    int d = threadIdx.x;
    float s1 = 0.f, s2 = 0.f, s3 = 0.f, s4 = 0.f;
    for (int k = 0; k < 128; k++) {
        float w1 = W1[k * 128 + d], w2 = W2[k * 128 + d];
        s1 += w1 * a1s[k];
        s2 += w1 * a1d[k];
        s3 += w2 * a2s[k];
        s4 += w2 * a2d[k];
    }
    g_wv[d] = s1; g_wv[128 + d] = s2; g_wv[256 + d] = s3; g_wv[384 + d] = s4;
}

__device__ __forceinline__ float leaky(float e) { return e > 0.f ? e : 0.2f * e; }

// ---------------- combined edge decomposition ------------------------------------
__device__ __forceinline__ bool decomp_edge(int i, const int* edge, const int* paper,
                                            const int* author, int E, int Ep, int Ea,
                                            int& s, int& d, int& conv1)
{
    if (i < E) { s = edge[i]; d = edge[E + i] + NS; conv1 = 1; return true; }
    i -= E;
    if (i < Ea) { s = author[i]; d = author[Ea + i]; conv1 = 1; return d >= NS; }
    i -= Ea;
    if (i < NT) { s = d = NS + i; conv1 = 1; return true; }
    i -= NT;
    if (i < E) { s = edge[E + i] + NS; d = edge[i]; conv1 = 0; return true; }
    i -= E;
    if (i < Ep) { s = paper[i]; d = paper[Ep + i]; conv1 = 0; return d < NS; }
    i -= Ep;
    if (i < NS) { s = d = i; conv1 = 0; return true; }
    return false;
}

__global__ void hist_k(const int* __restrict__ edge, const int* __restrict__ paper,
                       const int* __restrict__ author, int E, int Ep, int Ea, int T)
{
    int i = blockIdx.x * blockDim.x + threadIdx.x;
    if (i >= T) return;
    int s, d, c1;
    if (decomp_edge(i, edge, paper, author, E, Ep, Ea, s, d, c1))
        atomicAdd(&g_deg[d], 1);
}

__global__ void scan1_k()
{
    __shared__ int sm[256];
    int t = threadIdx.x;
    int i = blockIdx.x * 256 + t;
    int v = (i < NN) ? g_deg[i] : 0;
    sm[t] = v; __syncthreads();
#pragma unroll
    for (int off = 1; off < 256; off <<= 1) {
        int u = (t >= off) ? sm[t - off] : 0;
        __syncthreads();
        sm[t] += u;
        __syncthreads();
    }
    if (i < NN) g_rowptr[i] = sm[t] - v;
    if (t == 255) g_part[blockIdx.x] = sm[255];
}

__global__ void scan2_k(int nb)
{
    __shared__ int sm[512];
    int t = threadIdx.x;
    int v = (t < nb) ? g_part[t] : 0;
    sm[t] = v; __syncthreads();
#pragma unroll
    for (int off = 1; off < 512; off <<= 1) {
        int u = (t >= off) ? sm[t - off] : 0;
        __syncthreads();
        sm[t] += u;
        __syncthreads();
    }
    if (t < nb) g_part[t] = sm[t] - v;
}

__global__ void scan3_k()
{
    int i = blockIdx.x * 256 + threadIdx.x;
    if (i >= NN) return;
    int rp = g_rowptr[i] + g_part[blockIdx.x];
    g_rowptr[i] = rp;
    g_cur[i]    = rp;
}

__global__ void fill_k(const int* __restrict__ edge, const int* __restrict__ paper,
                       const int* __restrict__ author, int E, int Ep, int Ea, int T)
{
    int i = blockIdx.x * blockDim.x + threadIdx.x;
    if (i >= T) return;
    int s, d, c1;
    if (!decomp_edge(i, edge, paper, author, E, Ep, Ea, s, d, c1)) return;
    float e = c1 ? (g_sc[s] + g_sc[NN + d]) : (g_sc[2 * NN + s] + g_sc[3 * NN + d]);
    float w = __expf(leaky(e));
    int pos = atomicAdd(&g_cur[d], 1);
    if (pos < CAP) { g_esrc[pos] = s; g_ew[pos] = w; }
}

// ---------------- SpMM: warp per dst row; fp16 gather, f32 accumulate ------------
__global__ __launch_bounds__(256)
void spmm_k()
{
    int r    = (blockIdx.x * blockDim.x + threadIdx.x) >> 5;
    int lane = threadIdx.x & 31;
    if (r >= NN) return;
    int start = g_rowptr[r];
    int n     = g_deg[r];
    float4 acc = make_float4(0.f, 0.f, 0.f, 0.f);
    float  den = 0.f;
#pragma unroll 2
    for (int e = 0; e < n; e++) {
        int   src = __ldg(g_esrc + start + e);
        float w   = __ldg(g_ew   + start + e);
        uint2 u = *(const uint2*)(g_xh + (size_t)src * 128 + lane * 4);
        float2 f0 = __half22float2(*(__half2*)&u.x);
        float2 f1 = __half22float2(*(__half2*)&u.y);
        acc.x += w * f0.x; acc.y += w * f0.y;
        acc.z += w * f1.x; acc.w += w * f1.y;
        den   += w;
    }
    float rc = __frcp_rn(den + 1e-16f);
    acc.x *= rc; acc.y *= rc; acc.z *= rc; acc.w *= rc;
    *(float4*)(g_agg + (size_t)r * 128 + lane * 4) = acc;
}

// ---------------- host launch -----------------------------------------------------
extern "C" void kernel_launch(void* const* d_in, const int* in_sizes, int n_in,
                              void* d_out, int out_size)
{
    const int* edge   = (const int*)d_in[0];
    const int* paper  = (const int*)d_in[1];
    const int* author = (const int*)d_in[2];
    const float* x_s = (const float*)d_in[3];
    const float* x_t = (const float*)d_in[4];
    const float* Ws  = (const float*)d_in[5];
    const float* bs  = (const float*)d_in[6];
    const float* Wt  = (const float*)d_in[7];
    const float* bt  = (const float*)d_in[8];
    const float* W1  = (const float*)d_in[9];
    const float* a1s = (const float*)d_in[10];
    const float* a1d = (const float*)d_in[11];
    const float* W2  = (const float*)d_in[12];
    const float* a2s = (const float*)d_in[13];
    const float* a2d = (const float*)d_in[14];

    const int E  = in_sizes[0] / 2;
    const int Ep = in_sizes[1] / 2;
    const int Ea = in_sizes[2] / 2;
    const int T  = 2 * E + Ea + Ep + NS + NT;

    float *pagg, *psc;
    cudaGetSymbolAddress((void**)&pagg, g_agg);
    cudaGetSymbolAddress((void**)&psc,  g_sc);
    int* pdeg;
    cudaGetSymbolAddress((void**)&pdeg, g_deg);

    float* out = (float*)d_out;
    float* out_s = out;                     // conv2 result rows [0, NS)
    float* out_t = out + (size_t)NS * DD;   // conv1 result rows [NS, NN)

    const int GEMM_SMEM = (64 * 132 + 128 * 132) * 4;  // 101376 B
    cudaFuncSetAttribute((const void*)mma_gemm,
                         cudaFuncAttributeMaxDynamicSharedMemorySize, GEMM_SMEM);

    // 0. zero degree histogram + score accumulators
    cudaMemsetAsync(pdeg, 0, NN * sizeof(int), 0);
    cudaMemsetAsync(psc,  0, 4 * NN * sizeof(float), 0);

    // 1. score projection vectors, then input linears (fp16 x + fused scores)
    wvec_k<<<1, 128>>>(W1, a1s, a1d, W2, a2s, a2d);
    mma_gemm<<<(NS + 63) / 64, 256, GEMM_SMEM>>>(x_s, Ws, bs, nullptr, NS, 0, 1, 0);
    mma_gemm<<<(NT + 63) / 64, 256, GEMM_SMEM>>>(x_t, Wt, bt, nullptr, NT, 0, 1, NS);

    // 2. CSR build over both convs' kept edges
    const int TB = 256;
    hist_k<<<(T + TB - 1) / TB, TB>>>(edge, paper, author, E, Ep, Ea, T);
    scan1_k<<<NB, 256>>>();
    scan2_k<<<1, 512>>>(NB);
    scan3_k<<<NB, 256>>>();
    fill_k<<<(T + TB - 1) / TB, TB>>>(edge, paper, author, E, Ep, Ea, T);

    // 3. SpMM: normalized aggregation of fp16 x rows
    spmm_k<<<(NN * 32 + TB - 1) / TB, TB>>>();

    // 4. output transforms: out = relu( agg @ W^T )
    mma_gemm<<<(NT + 63) / 64, 256, GEMM_SMEM>>>(pagg + (size_t)NS * DD, W1, nullptr, out_t, NT, 1, 0, 0);
    mma_gemm<<<(NS + 63) / 64, 256, GEMM_SMEM>>>(pagg, W2, nullptr, out_s, NS, 1, 0, 0);
}

// round 12
// speedup vs baseline: 1.7231x; 1.2439x over previous
#include <cuda_runtime.h>
#include <cuda_fp16.h>
#include <cstdint>

#define NS 50000
#define NT 50000
#define NN 100000
#define DD 128
#define CAP 2200000
#define NB  ((NN + 255) / 256)

// ---------------- scratch (device globals: no runtime allocation) ----------------
static __device__ __half g_xh[NN * DD];   // transformed features, fp16 (gather source)
static __device__ float g_agg[NN * DD];   // rows [0,NS): conv2 agg; [NS,NN): conv1
static __device__ float g_sc [4 * NN];    // as1 | ad1 | as2 | ad2
static __device__ float g_wv [4 * DD];
static __device__ int   g_deg[NN];
static __device__ int   g_rowptr[NN];
static __device__ int   g_cur[NN];
static __device__ int   g_part[512];
static __device__ int   g_esrc[CAP];
static __device__ float g_ew  [CAP];

#define MMA_F16(d, a0, a1, a2, a3, b0, b1)                                       \
    asm volatile("mma.sync.aligned.m16n8k16.row.col.f32.f16.f16.f32 "            \
        "{%0,%1,%2,%3}, {%4,%5,%6,%7}, {%8,%9}, {%0,%1,%2,%3};"                  \
        : "+f"((d)[0]), "+f"((d)[1]), "+f"((d)[2]), "+f"((d)[3])                 \
        : "r"(a0), "r"(a1), "r"(a2), "r"(a3), "r"(b0), "r"(b1))

// =============== GEMM: C = A[M,128] @ W[128,128]^T, split-fp16 2-pass ============
// 64-row tile / 256 threads / 8 warps (4 m-tiles x 2 n-halves).
// A = Ah + Al (both fp16) fully compensated; W single fp16 rounding (~2^-11).
// Dual-segment grid: blocks [0,nb1) use set 1, rest use set 2 (merged launches).
// doScores=1: +bias, fp16 store to g_xh, fused attention scores. else: relu->C.
#define PH 136   // smem pitch in halves (272B: conflict-free, 8B aligned)
__global__ __launch_bounds__(256)
void mma_gemm(const float* __restrict__ A1, const float* __restrict__ W1p,
              const float* __restrict__ b1, float* __restrict__ C1, int M1, int so1,
              const float* __restrict__ A2, const float* __restrict__ W2p,
              const float* __restrict__ b2, float* __restrict__ C2, int M2, int so2,
              int nb1, int doRelu, int doScores)
{
    extern __shared__ __half sh[];
    __half* sAh = sh;              // 64  x PH
    __half* sAl = sh + 64 * PH;    // 64  x PH
    __half* sW  = sh + 128 * PH;   // 128 x PH   (W[n][k], fp16-rounded)

    const float* A; const float* W; const float* bias; float* C;
    int M, scoreOff, row0;
    if (blockIdx.x < nb1) {
        A = A1; W = W1p; bias = b1; C = C1; M = M1; scoreOff = so1;
        row0 = blockIdx.x * 64;
    } else {
        A = A2; W = W2p; bias = b2; C = C2; M = M2; scoreOff = so2;
        row0 = (blockIdx.x - nb1) * 64;
    }
    const int tid = threadIdx.x;

    // load W -> fp16 smem
    for (int i = tid; i < 4096; i += 256) {
        int n  = i >> 5;
        int k4 = (i & 31) << 2;
        float4 w = *(const float4*)(W + n * 128 + k4);
        uint2 p;
        *(__half2*)&p.x = __floats2half2_rn(w.x, w.y);
        *(__half2*)&p.y = __floats2half2_rn(w.z, w.w);
        *(uint2*)(sW + n * PH + k4) = p;
    }
    // load A -> split fp16 hi/lo smem
    for (int i = tid; i < 2048; i += 256) {
        int r  = i >> 5;
        int k4 = (i & 31) << 2;
        int gr = row0 + r;
        float4 v = make_float4(0.f, 0.f, 0.f, 0.f);
        if (gr < M) v = *(const float4*)(A + (size_t)gr * 128 + k4);
        __half hx = __float2half_rn(v.x), hy = __float2half_rn(v.y);
        __half hz = __float2half_rn(v.z), hw = __float2half_rn(v.w);
        uint2 hi, lo;
        *(__half2*)&hi.x = __halves2half2(hx, hy);
        *(__half2*)&hi.y = __halves2half2(hz, hw);
        *(__half2*)&lo.x = __floats2half2_rn(v.x - __half2float(hx), v.y - __half2float(hy));
        *(__half2*)&lo.y = __floats2half2_rn(v.z - __half2float(hz), v.w - __half2float(hw));
        *(uint2*)(sAh + r * PH + k4) = hi;
        *(uint2*)(sAl + r * PH + k4) = lo;
    }
    __syncthreads();

    const int wid  = tid >> 5;
    const int lane = tid & 31;
    const int mw   = wid & 3;          // m-tile (16 rows)
    const int nb   = (wid >> 2) * 64;  // n-half base
    const int g    = lane >> 2;
    const int tq   = lane & 3;

    float acc[8][4] = {};

#pragma unroll
    for (int ks = 0; ks < 8; ks++) {
        const int k0 = ks * 16;
        const int ra = (mw * 16 + g) * PH + k0 + 2 * tq;
        uint32_t ah0 = *(const uint32_t*)(sAh + ra);
        uint32_t ah1 = *(const uint32_t*)(sAh + ra + 8 * PH);
        uint32_t ah2 = *(const uint32_t*)(sAh + ra + 8);
        uint32_t ah3 = *(const uint32_t*)(sAh + ra + 8 * PH + 8);
        uint32_t al0 = *(const uint32_t*)(sAl + ra);
        uint32_t al1 = *(const uint32_t*)(sAl + ra + 8 * PH);
        uint32_t al2 = *(const uint32_t*)(sAl + ra + 8);
        uint32_t al3 = *(const uint32_t*)(sAl + ra + 8 * PH + 8);
#pragma unroll
        for (int nt = 0; nt < 8; nt++) {
            const int rb = (nb + nt * 8 + g) * PH + k0 + 2 * tq;
            uint32_t b0 = *(const uint32_t*)(sW + rb);
            uint32_t b1 = *(const uint32_t*)(sW + rb + 8);
            MMA_F16(acc[nt], ah0, ah1, ah2, ah3, b0, b1);
            MMA_F16(acc[nt], al0, al1, al2, al3, b0, b1);
        }
    }

    // epilogue
    const int r0 = row0 + mw * 16 + g;
    const int r1 = r0 + 8;
    float s0[4] = {}, s1[4] = {};

#pragma unroll
    for (int nt = 0; nt < 8; nt++) {
        int c = nb + nt * 8 + tq * 2;
        float bx = 0.f, by = 0.f;
        if (bias) { float2 b = *(const float2*)(bias + c); bx = b.x; by = b.y; }
        float o00 = acc[nt][0] + bx, o01 = acc[nt][1] + by;
        float o10 = acc[nt][2] + bx, o11 = acc[nt][3] + by;
        if (doScores) {
#pragma unroll
            for (int t = 0; t < 4; t++) {
                float2 w = *(const float2*)(g_wv + t * 128 + c);
                s0[t] += o00 * w.x + o01 * w.y;
                s1[t] += o10 * w.x + o11 * w.y;
            }
            if (r0 < M) *(__half2*)(g_xh + (size_t)(scoreOff + r0) * 128 + c) =
                __floats2half2_rn(o00, o01);
            if (r1 < M) *(__half2*)(g_xh + (size_t)(scoreOff + r1) * 128 + c) =
                __floats2half2_rn(o10, o11);
        } else {
            if (doRelu) {
                o00 = o00 > 0.f ? o00 : 0.f; o01 = o01 > 0.f ? o01 : 0.f;
                o10 = o10 > 0.f ? o10 : 0.f; o11 = o11 > 0.f ? o11 : 0.f;
            }
            if (r0 < M) *(float2*)(C + (size_t)r0 * 128 + c) = make_float2(o00, o01);
            if (r1 < M) *(float2*)(C + (size_t)r1 * 128 + c) = make_float2(o10, o11);
        }
    }

    if (doScores) {
#pragma unroll
        for (int t = 0; t < 4; t++) {
            s0[t] += __shfl_xor_sync(0xFFFFFFFFu, s0[t], 1);
            s0[t] += __shfl_xor_sync(0xFFFFFFFFu, s0[t], 2);
            s1[t] += __shfl_xor_sync(0xFFFFFFFFu, s1[t], 1);
            s1[t] += __shfl_xor_sync(0xFFFFFFFFu, s1[t], 2);
        }
        if (tq == 0) {
#pragma unroll
            for (int t = 0; t < 4; t++) {
                if (r0 < M) atomicAdd(&g_sc[t * NN + scoreOff + r0], s0[t]);
                if (r1 < M) atomicAdd(&g_sc[t * NN + scoreOff + r1], s1[t]);
            }
        }
    }
}

// ---------------- precompute wv = W^T a (4 vectors of 128) -----------------------
__global__ void wvec_k(const float* __restrict__ W1, const float* __restrict__ a1s,
                       const float* __restrict__ a1d,
                       const float* __restrict__ W2, const float* __restrict__ a2s,
                       const float* __restrict__ a2d)
{
    int d = threadIdx.x;
    float s1 = 0.f, s2 = 0.f, s3 = 0.f, s4 = 0.f;
    for (int k = 0; k < 128; k++) {
        float w1 = W1[k * 128 + d], w2 = W2[k * 128 + d];
        s1 += w1 * a1s[k];
        s2 += w1 * a1d[k];
        s3 += w2 * a2s[k];
        s4 += w2 * a2d[k];
    }
    g_wv[d] = s1; g_wv[128 + d] = s2; g_wv[256 + d] = s3; g_wv[384 + d] = s4;
}

__device__ __forceinline__ float leaky(float e) { return e > 0.f ? e : 0.2f * e; }

// ---------------- combined edge decomposition ------------------------------------
__device__ __forceinline__ bool decomp_edge(int i, const int* edge, const int* paper,
                                            const int* author, int E, int Ep, int Ea,
                                            int& s, int& d, int& conv1)
{
    if (i < E) { s = edge[i]; d = edge[E + i] + NS; conv1 = 1; return true; }
    i -= E;
    if (i < Ea) { s = author[i]; d = author[Ea + i]; conv1 = 1; return d >= NS; }
    i -= Ea;
    if (i < NT) { s = d = NS + i; conv1 = 1; return true; }
    i -= NT;
    if (i < E) { s = edge[E + i] + NS; d = edge[i]; conv1 = 0; return true; }
    i -= E;
    if (i < Ep) { s = paper[i]; d = paper[Ep + i]; conv1 = 0; return d < NS; }
    i -= Ep;
    if (i < NS) { s = d = i; conv1 = 0; return true; }
    return false;
}

__global__ void hist_k(const int* __restrict__ edge, const int* __restrict__ paper,
                       const int* __restrict__ author, int E, int Ep, int Ea, int T)
{
    int i = blockIdx.x * blockDim.x + threadIdx.x;
    if (i >= T) return;
    int s, d, c1;
    if (decomp_edge(i, edge, paper, author, E, Ep, Ea, s, d, c1))
        atomicAdd(&g_deg[d], 1);
}

__global__ void scan1_k()
{
    __shared__ int sm[256];
    int t = threadIdx.x;
    int i = blockIdx.x * 256 + t;
    int v = (i < NN) ? g_deg[i] : 0;
    sm[t] = v; __syncthreads();
#pragma unroll
    for (int off = 1; off < 256; off <<= 1) {
        int u = (t >= off) ? sm[t - off] : 0;
        __syncthreads();
        sm[t] += u;
        __syncthreads();
    }
    if (i < NN) g_rowptr[i] = sm[t] - v;
    if (t == 255) g_part[blockIdx.x] = sm[255];
}

__global__ void scan2_k(int nb)
{
    __shared__ int sm[512];
    int t = threadIdx.x;
    int v = (t < nb) ? g_part[t] : 0;
    sm[t] = v; __syncthreads();
#pragma unroll
    for (int off = 1; off < 512; off <<= 1) {
        int u = (t >= off) ? sm[t - off] : 0;
        __syncthreads();
        sm[t] += u;
        __syncthreads();
    }
    if (t < nb) g_part[t] = sm[t] - v;
}

__global__ void scan3_k()
{
    int i = blockIdx.x * 256 + threadIdx.x;
    if (i >= NN) return;
    int rp = g_rowptr[i] + g_part[blockIdx.x];
    g_rowptr[i] = rp;
    g_cur[i]    = rp;
}

__global__ void fill_k(const int* __restrict__ edge, const int* __restrict__ paper,
                       const int* __restrict__ author, int E, int Ep, int Ea, int T)
{
    int i = blockIdx.x * blockDim.x + threadIdx.x;
    if (i >= T) return;
    int s, d, c1;
    if (!decomp_edge(i, edge, paper, author, E, Ep, Ea, s, d, c1)) return;
    float e = c1 ? (g_sc[s] + g_sc[NN + d]) : (g_sc[2 * NN + s] + g_sc[3 * NN + d]);
    float w = __expf(leaky(e));
    int pos = atomicAdd(&g_cur[d], 1);
    if (pos < CAP) { g_esrc[pos] = s; g_ew[pos] = w; }
}

// ---------------- SpMM: warp per dst row, shfl-broadcast edges, ILP-4 gathers ----
__device__ __forceinline__ void gacc(float4& acc, float w, uint2 u)
{
    float2 f0 = __half22float2(*(__half2*)&u.x);
    float2 f1 = __half22float2(*(__half2*)&u.y);
    acc.x += w * f0.x; acc.y += w * f0.y;
    acc.z += w * f1.x; acc.w += w * f1.y;
}

__global__ __launch_bounds__(256)
void spmm_k()
{
    int r    = (blockIdx.x * blockDim.x + threadIdx.x) >> 5;
    int lane = threadIdx.x & 31;
    if (r >= NN) return;
    int start = g_rowptr[r];
    int n     = g_deg[r];
    float4 acc = make_float4(0.f, 0.f, 0.f, 0.f);
    float  den = 0.f;

    for (int base = 0; base < n; base += 32) {
        int m = n - base; if (m > 32) m = 32;
        int   src = 0; float wv = 0.f;
        if (lane < m) {
            src = g_esrc[start + base + lane];
            wv  = g_ew  [start + base + lane];
        }
        int j = 0;
        for (; j + 4 <= m; j += 4) {
            int   s0 = __shfl_sync(0xFFFFFFFFu, src, j);
            int   s1 = __shfl_sync(0xFFFFFFFFu, src, j + 1);
            int   s2 = __shfl_sync(0xFFFFFFFFu, src, j + 2);
            int   s3 = __shfl_sync(0xFFFFFFFFu, src, j + 3);
            float w0 = __shfl_sync(0xFFFFFFFFu, wv, j);
            float w1 = __shfl_sync(0xFFFFFFFFu, wv, j + 1);
            float w2 = __shfl_sync(0xFFFFFFFFu, wv, j + 2);
            float w3 = __shfl_sync(0xFFFFFFFFu, wv, j + 3);
            uint2 u0 = *(const uint2*)(g_xh + (size_t)s0 * 128 + lane * 4);
            uint2 u1 = *(const uint2*)(g_xh + (size_t)s1 * 128 + lane * 4);
            uint2 u2 = *(const uint2*)(g_xh + (size_t)s2 * 128 + lane * 4);
            uint2 u3 = *(const uint2*)(g_xh + (size_t)s3 * 128 + lane * 4);
            gacc(acc, w0, u0); gacc(acc, w1, u1);
            gacc(acc, w2, u2); gacc(acc, w3, u3);
            den += w0 + w1 + w2 + w3;
        }
        for (; j < m; j++) {
            int   s0 = __shfl_sync(0xFFFFFFFFu, src, j);
            float w0 = __shfl_sync(0xFFFFFFFFu, wv, j);
            uint2 u0 = *(const uint2*)(g_xh + (size_t)s0 * 128 + lane * 4);
            gacc(acc, w0, u0);
            den += w0;
        }
    }
    float rc = __frcp_rn(den + 1e-16f);
    acc.x *= rc; acc.y *= rc; acc.z *= rc; acc.w *= rc;
    *(float4*)(g_agg + (size_t)r * 128 + lane * 4) = acc;
}

// ---------------- host launch -----------------------------------------------------
extern "C" void kernel_launch(void* const* d_in, const int* in_sizes, int n_in,
                              void* d_out, int out_size)
{
    const int* edge   = (const int*)d_in[0];
    const int* paper  = (const int*)d_in[1];
    const int* author = (const int*)d_in[2];
    const float* x_s = (const float*)d_in[3];
    const float* x_t = (const float*)d_in[4];
    const float* Ws  = (const float*)d_in[5];
    const float* bs  = (const float*)d_in[6];
    const float* Wt  = (const float*)d_in[7];
    const float* bt  = (const float*)d_in[8];
    const float* W1  = (const float*)d_in[9];
    const float* a1s = (const float*)d_in[10];
    const float* a1d = (const float*)d_in[11];
    const float* W2  = (const float*)d_in[12];
    const float* a2s = (const float*)d_in[13];
    const float* a2d = (const float*)d_in[14];

    const int E  = in_sizes[0] / 2;
    const int Ep = in_sizes[1] / 2;
    const int Ea = in_sizes[2] / 2;
    const int T  = 2 * E + Ea + Ep + NS + NT;

    float *pagg, *psc;
    cudaGetSymbolAddress((void**)&pagg, g_agg);
    cudaGetSymbolAddress((void**)&psc,  g_sc);
    int* pdeg;
    cudaGetSymbolAddress((void**)&pdeg, g_deg);

    float* out = (float*)d_out;
    float* out_s = out;                     // conv2 result rows [0, NS)
    float* out_t = out + (size_t)NS * DD;   // conv1 result rows [NS, NN)

    const int GEMM_SMEM = (128 * PH + 128 * PH) * 2;  // 69632 B (hi+lo A, W)
    cudaFuncSetAttribute((const void*)mma_gemm,
                         cudaFuncAttributeMaxDynamicSharedMemorySize, GEMM_SMEM);

    // 0. zero degree histogram + score accumulators
    cudaMemsetAsync(pdeg, 0, NN * sizeof(int), 0);
    cudaMemsetAsync(psc,  0, 4 * NN * sizeof(float), 0);

    // 1. score projection vectors, then merged input linears (fp16 x + scores)
    wvec_k<<<1, 128>>>(W1, a1s, a1d, W2, a2s, a2d);
    const int nbS = (NS + 63) / 64, nbT = (NT + 63) / 64;
    mma_gemm<<<nbS + nbT, 256, GEMM_SMEM>>>(
        x_s, Ws, bs, nullptr, NS, 0,
        x_t, Wt, bt, nullptr, NT, NS,
        nbS, 0, 1);

    // 2. CSR build over both convs' kept edges
    const int TB = 256;
    hist_k<<<(T + TB - 1) / TB, TB>>>(edge, paper, author, E, Ep, Ea, T);
    scan1_k<<<NB, 256>>>();
    scan2_k<<<1, 512>>>(NB);
    scan3_k<<<NB, 256>>>();
    fill_k<<<(T + TB - 1) / TB, TB>>>(edge, paper, author, E, Ep, Ea, T);

    // 3. SpMM: normalized aggregation of fp16 x rows
    spmm_k<<<(NN * 32 + TB - 1) / TB, TB>>>();

    // 4. merged output transforms: out = relu( agg @ W^T )
    mma_gemm<<<nbT + nbS, 256, GEMM_SMEM>>>(
        pagg + (size_t)NS * DD, W1, nullptr, out_t, NT, 0,
        pagg, W2, nullptr, out_s, NS, 0,
        nbT, 1, 0);
}